// round 13
// baseline (speedup 1.0000x reference)
#include <cuda_runtime.h>
#include <cuda_fp16.h>
#include <math.h>

#define NN 10000
#define EE 160000
#define FIN 70
#define HIDC 256
#define NHEADS 4
#define D1 1024   // NHEADS*HIDC

// ---------------- scratch (device globals; no allocations) ----------------
__device__ __half g_h1f[(size_t)NN * D1];   // layer1 pre-attention features (fp16)
__device__ __half g_x1f[(size_t)NN * D1];   // layer1 output relu (fp16)
__device__ __half g_h2f[(size_t)NN * HIDC]; // layer2 pre-attention features (fp16)
__device__ __half g_w2hT[(size_t)HIDC * D1];// W2 transposed fp16: [n][k]
__device__ float g_as1[NN * NHEADS];
__device__ float g_ad1[NN * NHEADS];
__device__ float g_as2[NN];
__device__ float g_ad2[NN];
__device__ int   g_cnt[NN];
__device__ int   g_rowptr[NN + 1];
__device__ int   g_fill[NN];
__device__ int   g_csrsrc[EE];
__device__ float g_pooled[HIDC];

// ---------------- mma helpers ----------------
__device__ __forceinline__ float to_tf32(float x) {
    asm("cvt.rna.tf32.f32 %0, %0;" : "+f"(x));
    return x;
}

__device__ __forceinline__ void mma_tf32(float d[4], const float a[4], const float b[2]) {
    unsigned const* A = reinterpret_cast<unsigned const*>(a);
    unsigned const* B = reinterpret_cast<unsigned const*>(b);
    asm volatile(
        "mma.sync.aligned.m16n8k8.row.col.f32.tf32.tf32.f32 "
        "{%0,%1,%2,%3},{%4,%5,%6,%7},{%8,%9},{%0,%1,%2,%3};"
        : "+f"(d[0]), "+f"(d[1]), "+f"(d[2]), "+f"(d[3])
        : "r"(A[0]), "r"(A[1]), "r"(A[2]), "r"(A[3]), "r"(B[0]), "r"(B[1]));
}

__device__ __forceinline__ void mma_f16(float d[4], const unsigned a[4], const unsigned b[2]) {
    asm volatile(
        "mma.sync.aligned.m16n8k16.row.col.f32.f16.f16.f32 "
        "{%0,%1,%2,%3},{%4,%5,%6,%7},{%8,%9},{%0,%1,%2,%3};"
        : "+f"(d[0]), "+f"(d[1]), "+f"(d[2]), "+f"(d[3])
        : "r"(a[0]), "r"(a[1]), "r"(a[2]), "r"(a[3]), "r"(b[0]), "r"(b[1]));
}

// ---------------- preamble: zero scratch + W2 -> fp16 transposed ----------------
__global__ void k_init(const float* __restrict__ W2) {
    int i = blockIdx.x * blockDim.x + threadIdx.x;    // D1*HIDC threads
    if (i < D1 * HIDC) {
        int k = i >> 8, n = i & 255;
        g_w2hT[(size_t)n * D1 + k] = __float2half(W2[i]);
    }
    if (i < NN) { g_cnt[i] = 0; g_as2[i] = 0.f; g_ad2[i] = 0.f; }
    if (i < NN * NHEADS) { g_as1[i] = 0.f; g_ad1[i] = 0.f; }
    if (i < HIDC) g_pooled[i] = 0.f;
}

// ---------------- CSR build ----------------
__global__ void k_hist(const int* __restrict__ ei) {
    int e = blockIdx.x * blockDim.x + threadIdx.x;
    if (e < EE) atomicAdd(&g_cnt[ei[EE + e]], 1);
}

// single-pass scan: 1024 threads x 10 elements each (covers NN=10000)
#define SCAN_C 10
__global__ void k_scan() {
    __shared__ int wsum[32];
    int t = threadIdx.x, lane = t & 31, w = t >> 5;
    int base = t * SCAN_C;
    int v[SCAN_C];
    int s = 0;
#pragma unroll
    for (int k = 0; k < SCAN_C; k++) {
        int i = base + k;
        v[k] = (i < NN) ? g_cnt[i] : 0;
        s += v[k];
    }
    // block-wide exclusive scan of per-thread sums
    int x = s;
#pragma unroll
    for (int o = 1; o < 32; o <<= 1) {
        int y = __shfl_up_sync(0xffffffffu, x, o);
        if (lane >= o) x += y;
    }
    if (lane == 31) wsum[w] = x;
    __syncthreads();
    if (w == 0) {
        int ws = wsum[lane];
#pragma unroll
        for (int o = 1; o < 32; o <<= 1) {
            int y = __shfl_up_sync(0xffffffffu, ws, o);
            if (lane >= o) ws += y;
        }
        wsum[lane] = ws;
    }
    __syncthreads();
    int run = x - s + (w ? wsum[w - 1] : 0);   // exclusive prefix for this thread
#pragma unroll
    for (int k = 0; k < SCAN_C; k++) {
        int i = base + k;
        if (i < NN) { g_rowptr[i] = run; g_fill[i] = run; }
        run += v[k];
    }
    if (t == 1023) g_rowptr[NN] = run;
}

__global__ void k_fill(const int* __restrict__ ei) {
    int e = blockIdx.x * blockDim.x + threadIdx.x;
    if (e < EE) {
        int d = ei[EE + e];
        int p = atomicAdd(&g_fill[d], 1);
        g_csrsrc[p] = ei[e];
    }
}

// ---------------- GEMM1 (tf32 TC) + fused dots1 + fp16 store ----------------
#define G1_BM 64
#define G1_BN 64
#define G1_BK 72
__global__ void __launch_bounds__(256) k_gemm1_tc(const float* __restrict__ X,
                                                  const float* __restrict__ W1,
                                                  const float* __restrict__ att_s,
                                                  const float* __restrict__ att_d) {
    __shared__ float As[G1_BM][76];
    __shared__ float Bs[G1_BK][72];
    int m0 = blockIdx.y * G1_BM, n0 = blockIdx.x * G1_BN;
    int t = threadIdx.x;
    int warp = t >> 5, lane = t & 31;
    int g = lane >> 2, tig = lane & 3;
    int warp_m = (warp & 1) * 32;
    int warp_n = (warp >> 1) * 16;

    for (int idx = t; idx < G1_BM * G1_BK; idx += 256) {
        int r = idx / G1_BK, c = idx - r * G1_BK;
        int gm = m0 + r;
        float v = 0.f;
        if (c < FIN && gm < NN) v = X[(size_t)gm * FIN + c];
        As[r][c] = to_tf32(v);
    }
    for (int idx = t; idx < G1_BK * G1_BN; idx += 256) {
        int k = idx >> 6, n = idx & 63;
        float v = (k < FIN) ? W1[(size_t)k * D1 + n0 + n] : 0.f;
        Bs[k][n] = to_tf32(v);
    }
    __syncthreads();

    float acc[2][2][4];
#pragma unroll
    for (int i = 0; i < 2; i++)
#pragma unroll
        for (int j = 0; j < 2; j++)
#pragma unroll
            for (int q = 0; q < 4; q++) acc[i][j][q] = 0.f;

#pragma unroll
    for (int ks = 0; ks < 9; ks++) {
        int k = ks * 8;
        float a[2][4], b[2][2];
#pragma unroll
        for (int mt = 0; mt < 2; mt++) {
            int row = warp_m + mt * 16 + g;
            a[mt][0] = As[row][k + tig];
            a[mt][1] = As[row + 8][k + tig];
            a[mt][2] = As[row][k + 4 + tig];
            a[mt][3] = As[row + 8][k + 4 + tig];
        }
#pragma unroll
        for (int nt = 0; nt < 2; nt++) {
            int col = warp_n + nt * 8 + g;
            b[nt][0] = Bs[k + tig][col];
            b[nt][1] = Bs[k + 4 + tig][col];
        }
#pragma unroll
        for (int mt = 0; mt < 2; mt++)
#pragma unroll
            for (int nt = 0; nt < 2; nt++)
                mma_tf32(acc[mt][nt], a[mt], b[nt]);
    }

    // fused dots1 partials + fp16 feature store
    __shared__ float sAs[G1_BM], sAd[G1_BM];
    if (t < G1_BM) { sAs[t] = 0.f; sAd[t] = 0.f; }
    __syncthreads();
    int h = n0 >> 8;
    const float* avs = att_s + h * HIDC + (n0 & 255);
    const float* avd = att_d + h * HIDC + (n0 & 255);
#pragma unroll
    for (int mt = 0; mt < 2; mt++) {
        float ps0 = 0.f, pd0 = 0.f, ps1 = 0.f, pd1 = 0.f;
#pragma unroll
        for (int nt = 0; nt < 2; nt++) {
            int c = warp_n + nt * 8 + 2 * tig;
            float s0 = avs[c], s1 = avs[c + 1], dv0 = avd[c], dv1 = avd[c + 1];
            ps0 += acc[mt][nt][0] * s0 + acc[mt][nt][1] * s1;
            pd0 += acc[mt][nt][0] * dv0 + acc[mt][nt][1] * dv1;
            ps1 += acc[mt][nt][2] * s0 + acc[mt][nt][3] * s1;
            pd1 += acc[mt][nt][2] * dv0 + acc[mt][nt][3] * dv1;
        }
        int lr0 = warp_m + mt * 16 + g, lr1 = lr0 + 8;
        atomicAdd(&sAs[lr0], ps0); atomicAdd(&sAd[lr0], pd0);
        atomicAdd(&sAs[lr1], ps1); atomicAdd(&sAd[lr1], pd1);
        int r0 = m0 + lr0, r1 = m0 + lr1;
#pragma unroll
        for (int nt = 0; nt < 2; nt++) {
            int c = n0 + warp_n + nt * 8 + 2 * tig;
            if (r0 < NN) *(__half2*)&g_h1f[(size_t)r0 * D1 + c] =
                __floats2half2_rn(acc[mt][nt][0], acc[mt][nt][1]);
            if (r1 < NN) *(__half2*)&g_h1f[(size_t)r1 * D1 + c] =
                __floats2half2_rn(acc[mt][nt][2], acc[mt][nt][3]);
        }
    }
    __syncthreads();
    if (t < G1_BM && m0 + t < NN) {
        atomicAdd(&g_as1[(m0 + t) * NHEADS + h], sAs[t]);
        atomicAdd(&g_ad1[(m0 + t) * NHEADS + h], sAd[t]);
    }
}

// ---------------- GEMM2 (fp16 TC) + fused dots2 + fp16 store ----------------
__global__ void __launch_bounds__(256) k_gemm2_hf(const float* __restrict__ att_s,
                                                  const float* __restrict__ att_d) {
    __shared__ __half As2[128][40];
    __shared__ __half Bs2[128][40];
    int m0 = blockIdx.y * 128, n0 = blockIdx.x * 128;
    int t = threadIdx.x;
    int warp = t >> 5, lane = t & 31;
    int g = lane >> 2, tig = lane & 3;
    int warp_m = (warp & 1) * 64;
    int warp_n = (warp >> 1) * 32;

    float acc[4][4][4];
#pragma unroll
    for (int i = 0; i < 4; i++)
#pragma unroll
        for (int j = 0; j < 4; j++)
#pragma unroll
            for (int q = 0; q < 4; q++) acc[i][j][q] = 0.f;

    int ar = t >> 1, ak = (t & 1) * 16;

    for (int kb = 0; kb < D1; kb += 32) {
        {
            int gm = m0 + ar;
            uint4 v0 = make_uint4(0u, 0u, 0u, 0u), v1 = v0;
            if (gm < NN) {
                v0 = *(const uint4*)&g_x1f[(size_t)gm * D1 + kb + ak];
                v1 = *(const uint4*)&g_x1f[(size_t)gm * D1 + kb + ak + 8];
            }
            *(uint4*)&As2[ar][ak] = v0;
            *(uint4*)&As2[ar][ak + 8] = v1;
            uint4 w0 = *(const uint4*)&g_w2hT[(size_t)(n0 + ar) * D1 + kb + ak];
            uint4 w1 = *(const uint4*)&g_w2hT[(size_t)(n0 + ar) * D1 + kb + ak + 8];
            *(uint4*)&Bs2[ar][ak] = w0;
            *(uint4*)&Bs2[ar][ak + 8] = w1;
        }
        __syncthreads();
#pragma unroll
        for (int ks = 0; ks < 2; ks++) {
            int kk = ks * 16;
            unsigned a[4][4], b[4][2];
#pragma unroll
            for (int mt = 0; mt < 4; mt++) {
                int row = warp_m + mt * 16 + g;
                a[mt][0] = *(const unsigned*)&As2[row][kk + 2 * tig];
                a[mt][1] = *(const unsigned*)&As2[row + 8][kk + 2 * tig];
                a[mt][2] = *(const unsigned*)&As2[row][kk + 8 + 2 * tig];
                a[mt][3] = *(const unsigned*)&As2[row + 8][kk + 8 + 2 * tig];
            }
#pragma unroll
            for (int nt = 0; nt < 4; nt++) {
                int col = warp_n + nt * 8 + g;
                b[nt][0] = *(const unsigned*)&Bs2[col][kk + 2 * tig];
                b[nt][1] = *(const unsigned*)&Bs2[col][kk + 8 + 2 * tig];
            }
#pragma unroll
            for (int mt = 0; mt < 4; mt++)
#pragma unroll
                for (int nt = 0; nt < 4; nt++)
                    mma_f16(acc[mt][nt], a[mt], b[nt]);
        }
        __syncthreads();
    }

    __shared__ float sAs[128], sAd[128];
    if (t < 128) { sAs[t] = 0.f; sAd[t] = 0.f; }
    __syncthreads();
    const float* avs = att_s + n0;
    const float* avd = att_d + n0;
#pragma unroll
    for (int mt = 0; mt < 4; mt++) {
        float ps0 = 0.f, pd0 = 0.f, ps1 = 0.f, pd1 = 0.f;
#pragma unroll
        for (int nt = 0; nt < 4; nt++) {
            int c = warp_n + nt * 8 + 2 * tig;
            float s0 = avs[c], s1 = avs[c + 1], dv0 = avd[c], dv1 = avd[c + 1];
            ps0 += acc[mt][nt][0] * s0 + acc[mt][nt][1] * s1;
            pd0 += acc[mt][nt][0] * dv0 + acc[mt][nt][1] * dv1;
            ps1 += acc[mt][nt][2] * s0 + acc[mt][nt][3] * s1;
            pd1 += acc[mt][nt][2] * dv0 + acc[mt][nt][3] * dv1;
        }
        int lr0 = warp_m + mt * 16 + g, lr1 = lr0 + 8;
        atomicAdd(&sAs[lr0], ps0); atomicAdd(&sAd[lr0], pd0);
        atomicAdd(&sAs[lr1], ps1); atomicAdd(&sAd[lr1], pd1);
        int r0 = m0 + lr0, r1 = m0 + lr1;
#pragma unroll
        for (int nt = 0; nt < 4; nt++) {
            int c = n0 + warp_n + nt * 8 + 2 * tig;
            if (r0 < NN) *(__half2*)&g_h2f[(size_t)r0 * HIDC + c] =
                __floats2half2_rn(acc[mt][nt][0], acc[mt][nt][1]);
            if (r1 < NN) *(__half2*)&g_h2f[(size_t)r1 * HIDC + c] =
                __floats2half2_rn(acc[mt][nt][2], acc[mt][nt][3]);
        }
    }
    __syncthreads();
    if (t < 128 && m0 + t < NN) {
        atomicAdd(&g_as2[m0 + t], sAs[t]);
        atomicAdd(&g_ad2[m0 + t], sAd[t]);
    }
}

// ---------------- fused softmax + aggregation, layer 1 (no max pass) ----------------
__global__ void __launch_bounds__(256) k_agg1(const float* __restrict__ b1) {
    int dd = blockIdx.x, t = threadIdx.x;
    int beg = g_rowptr[dd], deg = g_rowptr[dd + 1] - beg, total = deg + 1;
    const float4* as4 = (const float4*)g_as1;
    float4 adv4 = ((const float4*)g_ad1)[dd];
    float ad[4] = {adv4.x, adv4.y, adv4.z, adv4.w};

    __shared__ float sred[8][4];
    int lane = t & 31, w = t >> 5;

    __shared__ float4 sw[256];
    __shared__ int ssrc[256];
    int hh = t >> 6;                 // head 0..3
    int f0 = (t & 63) * 4;           // feature start within head
    const size_t hoff = (size_t)hh * HIDC + f0;
    float acc[4] = {0.f, 0.f, 0.f, 0.f};
    float dl[4] = {0.f, 0.f, 0.f, 0.f};
    for (int base = 0; base < total; base += 256) {
        int j = base + t;
        int cn = min(256, total - base);
        if (j < total) {
            int s = (j < deg) ? g_csrsrc[beg + j] : dd;
            float4 a4 = as4[s];
            float e, w0, w1, w2, w3;
            e = a4.x + ad[0]; e = e > 0.f ? e : 0.2f * e; w0 = __expf(e); dl[0] += w0;
            e = a4.y + ad[1]; e = e > 0.f ? e : 0.2f * e; w1 = __expf(e); dl[1] += w1;
            e = a4.z + ad[2]; e = e > 0.f ? e : 0.2f * e; w2 = __expf(e); dl[2] += w2;
            e = a4.w + ad[3]; e = e > 0.f ? e : 0.2f * e; w3 = __expf(e); dl[3] += w3;
            sw[t] = make_float4(w0, w1, w2, w3);
            ssrc[t] = s;
        }
        __syncthreads();
#pragma unroll 8
        for (int j2 = 0; j2 < cn; j2++) {
            int s = ssrc[j2];
            float wv = ((const float*)&sw[j2])[hh];
            uint2 u = *(const uint2*)&g_h1f[(size_t)s * D1 + hoff];
            float2 fA = __half22float2(*(const __half2*)&u.x);
            float2 fB = __half22float2(*(const __half2*)&u.y);
            acc[0] += wv * fA.x; acc[1] += wv * fA.y;
            acc[2] += wv * fB.x; acc[3] += wv * fB.y;
        }
        __syncthreads();
    }
#pragma unroll
    for (int h = 0; h < 4; h++)
        for (int o = 16; o; o >>= 1) dl[h] += __shfl_xor_sync(0xffffffffu, dl[h], o);
    if (lane == 0) { sred[w][0] = dl[0]; sred[w][1] = dl[1]; sred[w][2] = dl[2]; sred[w][3] = dl[3]; }
    __syncthreads();
    __shared__ float den_s[4];
    if (t < 4) {
        float s = 0.f;
        for (int i = 0; i < 8; i++) s += sred[i][t];
        den_s[t] = s;
    }
    __syncthreads();
    {
        float inv = 1.0f / (den_s[hh] + 1e-16f);
        const float* bp = b1 + hh * HIDC + f0;
        float o0 = acc[0] * inv + bp[0];
        float o1 = acc[1] * inv + bp[1];
        float o2 = acc[2] * inv + bp[2];
        float o3 = acc[3] * inv + bp[3];
        o0 = o0 > 0.f ? o0 : 0.f; o1 = o1 > 0.f ? o1 : 0.f;
        o2 = o2 > 0.f ? o2 : 0.f; o3 = o3 > 0.f ? o3 : 0.f;
        __half2 h01 = __floats2half2_rn(o0, o1);
        __half2 h23 = __floats2half2_rn(o2, o3);
        uint2 uo = make_uint2(*(unsigned*)&h01, *(unsigned*)&h23);
        *(uint2*)&g_x1f[(size_t)dd * D1 + hoff] = uo;
    }
}

// ---------------- fused softmax + aggregation + pooling, layer 2 (no max pass) ----------------
__global__ void __launch_bounds__(256) k_agg2(const float* __restrict__ b2) {
    int dd = blockIdx.x, t = threadIdx.x;
    int beg = g_rowptr[dd], deg = g_rowptr[dd + 1] - beg, total = deg + 1;
    float adv = g_ad2[dd];
    __shared__ float sred[8];
    int lane = t & 31, w = t >> 5;

    __shared__ float sw[256];
    __shared__ int ssrc[256];
    float acc = 0.f, dl = 0.f;
    for (int base = 0; base < total; base += 256) {
        int j = base + t;
        int cn = min(256, total - base);
        if (j < total) {
            int s = (j < deg) ? g_csrsrc[beg + j] : dd;
            float e = g_as2[s] + adv; e = e > 0.f ? e : 0.2f * e;
            float wv = __expf(e);
            sw[t] = wv; ssrc[t] = s; dl += wv;
        }
        __syncthreads();
#pragma unroll 8
        for (int j2 = 0; j2 < cn; j2++) {
            acc += sw[j2] * __half2float(g_h2f[(size_t)ssrc[j2] * HIDC + t]);
        }
        __syncthreads();
    }
    for (int o = 16; o; o >>= 1) dl += __shfl_xor_sync(0xffffffffu, dl, o);
    if (lane == 0) sred[w] = dl;
    __syncthreads();
    __shared__ float den_s;
    if (t == 0) {
        float s = 0.f;
        for (int i = 0; i < 8; i++) s += sred[i];
        den_s = s;
    }
    __syncthreads();
    float o = acc / (den_s + 1e-16f) + b2[t];
    o = o > 0.f ? o : 0.f;
    atomicAdd(&g_pooled[t], o);
}

// ---------------- MLP head ----------------
__global__ void k_final(const float* __restrict__ Wv1, const float* __restrict__ bv1,
                        const float* __restrict__ Wv2, const float* __restrict__ bv2,
                        float* __restrict__ out) {
    __shared__ float red[128];
    int j = threadIdx.x;  // 128
    float acc = bv1[j];
    const float inv_n = 1.0f / (float)NN;
    for (int c = 0; c < HIDC; c++)
        acc += (g_pooled[c] * inv_n) * Wv1[c * 128 + j];
    float x = acc;
    float g = 0.5f * x * (1.0f + erff(x * 0.70710678118654752f));
    red[j] = g * Wv2[j];
    __syncthreads();
    for (int o = 64; o; o >>= 1) {
        if (j < o) red[j] += red[j + o];
        __syncthreads();
    }
    if (j == 0) out[0] = red[0] + bv2[0];
}

// ---------------- launch ----------------
extern "C" void kernel_launch(void* const* d_in, const int* in_sizes, int n_in,
                              void* d_out, int out_size) {
    const float* X   = (const float*)d_in[0];
    const int*   ei  = (const int*)d_in[1];
    // d_in[2] = edge_attr (ignored: GATConv has no edge_dim)
    const float* W1  = (const float*)d_in[3];
    const float* as1 = (const float*)d_in[4];
    const float* ad1 = (const float*)d_in[5];
    const float* b1  = (const float*)d_in[6];
    const float* W2  = (const float*)d_in[7];
    const float* as2 = (const float*)d_in[8];
    const float* ad2 = (const float*)d_in[9];
    const float* b2  = (const float*)d_in[10];
    const float* Wv1 = (const float*)d_in[11];
    const float* bv1 = (const float*)d_in[12];
    const float* Wv2 = (const float*)d_in[13];
    const float* bv2 = (const float*)d_in[14];
    float* out = (float*)d_out;

    k_init<<<(D1 * HIDC + 255) / 256, 256>>>(W2);
    k_hist<<<(EE + 255) / 256, 256>>>(ei);
    k_scan<<<1, 1024>>>();
    k_fill<<<(EE + 255) / 256, 256>>>(ei);

    k_gemm1_tc<<<dim3(D1 / G1_BN, (NN + G1_BM - 1) / G1_BM), 256>>>(X, W1, as1, ad1);
    k_agg1<<<NN, 256>>>(b1);

    k_gemm2_hf<<<dim3(2, (NN + 127) / 128), 256>>>(as2, ad2);
    k_agg2<<<NN, 256>>>(b2);

    k_final<<<1, 128>>>(Wv1, bv1, Wv2, bv2, out);
}

// round 14
// speedup vs baseline: 1.0229x; 1.0229x over previous
#include <cuda_runtime.h>
#include <cuda_fp16.h>
#include <math.h>

#define NN 10000
#define EE 160000
#define FIN 70
#define HIDC 256
#define NHEADS 4
#define D1 1024   // NHEADS*HIDC

// ---------------- scratch (device globals; no allocations) ----------------
__device__ __half g_h1f[(size_t)NN * D1];   // layer1 pre-attention features (fp16)
__device__ __half g_x1f[(size_t)NN * D1];   // layer1 output relu (fp16)
__device__ __half g_h2f[(size_t)NN * HIDC]; // layer2 pre-attention features (fp16)
__device__ __half g_w2hT[(size_t)HIDC * D1];// W2 transposed fp16: [n][k]
__device__ float g_as1[NN * NHEADS];
__device__ float g_ad1[NN * NHEADS];
__device__ float g_as2[NN];
__device__ float g_ad2[NN];
__device__ int   g_cnt[NN];
__device__ int   g_rowptr[NN + 1];
__device__ int   g_fill[NN];
__device__ int   g_csrsrc[EE];
__device__ float g_pooled[HIDC];

// ---------------- mma helpers ----------------
__device__ __forceinline__ float to_tf32(float x) {
    asm("cvt.rna.tf32.f32 %0, %0;" : "+f"(x));
    return x;
}

__device__ __forceinline__ void mma_tf32(float d[4], const float a[4], const float b[2]) {
    unsigned const* A = reinterpret_cast<unsigned const*>(a);
    unsigned const* B = reinterpret_cast<unsigned const*>(b);
    asm volatile(
        "mma.sync.aligned.m16n8k8.row.col.f32.tf32.tf32.f32 "
        "{%0,%1,%2,%3},{%4,%5,%6,%7},{%8,%9},{%0,%1,%2,%3};"
        : "+f"(d[0]), "+f"(d[1]), "+f"(d[2]), "+f"(d[3])
        : "r"(A[0]), "r"(A[1]), "r"(A[2]), "r"(A[3]), "r"(B[0]), "r"(B[1]));
}

__device__ __forceinline__ void mma_f16(float d[4], const unsigned a[4], const unsigned b[2]) {
    asm volatile(
        "mma.sync.aligned.m16n8k16.row.col.f32.f16.f16.f32 "
        "{%0,%1,%2,%3},{%4,%5,%6,%7},{%8,%9},{%0,%1,%2,%3};"
        : "+f"(d[0]), "+f"(d[1]), "+f"(d[2]), "+f"(d[3])
        : "r"(a[0]), "r"(a[1]), "r"(a[2]), "r"(a[3]), "r"(b[0]), "r"(b[1]));
}

// ---------------- preamble: zero scratch + W2 -> fp16 transposed ----------------
__global__ void k_init(const float* __restrict__ W2) {
    cudaTriggerProgrammaticLaunchCompletion();   // let hist launch + load ei early
    int i = blockIdx.x * blockDim.x + threadIdx.x;    // D1*HIDC threads
    if (i < D1 * HIDC) {
        int k = i >> 8, n = i & 255;
        g_w2hT[(size_t)n * D1 + k] = __float2half(W2[i]);
    }
    if (i < NN) { g_cnt[i] = 0; g_as2[i] = 0.f; g_ad2[i] = 0.f; }
    if (i < NN * NHEADS) { g_as1[i] = 0.f; g_ad1[i] = 0.f; }
    if (i < HIDC) g_pooled[i] = 0.f;
}

// ---------------- CSR build ----------------
__global__ void k_hist(const int* __restrict__ ei) {
    int e = blockIdx.x * blockDim.x + threadIdx.x;
    int d = (e < EE) ? ei[EE + e] : 0;           // independent load, overlaps k_init
    cudaGridDependencySynchronize();             // wait: g_cnt zeroed
    if (e < EE) atomicAdd(&g_cnt[d], 1);
}

// single-pass scan: 1024 threads x 10 elements each (covers NN=10000)
#define SCAN_C 10
__global__ void k_scan() {
    cudaTriggerProgrammaticLaunchCompletion();   // let fill launch + load ei early
    cudaGridDependencySynchronize();             // wait: hist complete
    __shared__ int wsum[32];
    int t = threadIdx.x, lane = t & 31, w = t >> 5;
    int base = t * SCAN_C;
    int v[SCAN_C];
    int s = 0;
#pragma unroll
    for (int k = 0; k < SCAN_C; k++) {
        int i = base + k;
        v[k] = (i < NN) ? g_cnt[i] : 0;
        s += v[k];
    }
    int x = s;
#pragma unroll
    for (int o = 1; o < 32; o <<= 1) {
        int y = __shfl_up_sync(0xffffffffu, x, o);
        if (lane >= o) x += y;
    }
    if (lane == 31) wsum[w] = x;
    __syncthreads();
    if (w == 0) {
        int ws = wsum[lane];
#pragma unroll
        for (int o = 1; o < 32; o <<= 1) {
            int y = __shfl_up_sync(0xffffffffu, ws, o);
            if (lane >= o) ws += y;
        }
        wsum[lane] = ws;
    }
    __syncthreads();
    int run = x - s + (w ? wsum[w - 1] : 0);
#pragma unroll
    for (int k = 0; k < SCAN_C; k++) {
        int i = base + k;
        if (i < NN) { g_rowptr[i] = run; g_fill[i] = run; }
        run += v[k];
    }
    if (t == 1023) g_rowptr[NN] = run;
}

__global__ void k_fill(const int* __restrict__ ei) {
    cudaTriggerProgrammaticLaunchCompletion();   // let gemm1 start its tile work NOW
    int e = blockIdx.x * blockDim.x + threadIdx.x;
    int d = 0, s = 0;
    if (e < EE) { d = ei[EE + e]; s = ei[e]; }   // independent loads, overlap scan
    cudaGridDependencySynchronize();             // wait: g_fill ready
    if (e < EE) {
        int p = atomicAdd(&g_fill[d], 1);
        g_csrsrc[p] = s;
    }
}

// ---------------- GEMM1 (tf32 TC) + fused dots1 + fp16 store ----------------
// Main body (tile loads + mma) reads only harness inputs -> runs concurrently
// with the CSR chain under PDL; gridsync guards only the g_as1/g_ad1 atomics.
#define G1_BM 64
#define G1_BN 64
#define G1_BK 72
__global__ void __launch_bounds__(256) k_gemm1_tc(const float* __restrict__ X,
                                                  const float* __restrict__ W1,
                                                  const float* __restrict__ att_s,
                                                  const float* __restrict__ att_d) {
    __shared__ float As[G1_BM][76];
    __shared__ float Bs[G1_BK][72];
    int m0 = blockIdx.y * G1_BM, n0 = blockIdx.x * G1_BN;
    int t = threadIdx.x;
    int warp = t >> 5, lane = t & 31;
    int g = lane >> 2, tig = lane & 3;
    int warp_m = (warp & 1) * 32;
    int warp_n = (warp >> 1) * 16;

    for (int idx = t; idx < G1_BM * G1_BK; idx += 256) {
        int r = idx / G1_BK, c = idx - r * G1_BK;
        int gm = m0 + r;
        float v = 0.f;
        if (c < FIN && gm < NN) v = X[(size_t)gm * FIN + c];
        As[r][c] = to_tf32(v);
    }
    for (int idx = t; idx < G1_BK * G1_BN; idx += 256) {
        int k = idx >> 6, n = idx & 63;
        float v = (k < FIN) ? W1[(size_t)k * D1 + n0 + n] : 0.f;
        Bs[k][n] = to_tf32(v);
    }
    __syncthreads();

    float acc[2][2][4];
#pragma unroll
    for (int i = 0; i < 2; i++)
#pragma unroll
        for (int j = 0; j < 2; j++)
#pragma unroll
            for (int q = 0; q < 4; q++) acc[i][j][q] = 0.f;

#pragma unroll
    for (int ks = 0; ks < 9; ks++) {
        int k = ks * 8;
        float a[2][4], b[2][2];
#pragma unroll
        for (int mt = 0; mt < 2; mt++) {
            int row = warp_m + mt * 16 + g;
            a[mt][0] = As[row][k + tig];
            a[mt][1] = As[row + 8][k + tig];
            a[mt][2] = As[row][k + 4 + tig];
            a[mt][3] = As[row + 8][k + 4 + tig];
        }
#pragma unroll
        for (int nt = 0; nt < 2; nt++) {
            int col = warp_n + nt * 8 + g;
            b[nt][0] = Bs[k + tig][col];
            b[nt][1] = Bs[k + 4 + tig][col];
        }
#pragma unroll
        for (int mt = 0; mt < 2; mt++)
#pragma unroll
            for (int nt = 0; nt < 2; nt++)
                mma_tf32(acc[mt][nt], a[mt], b[nt]);
    }

    cudaGridDependencySynchronize();   // wait: k_init zeroed g_as1/g_ad1 (CSR chain done too)

    // fused dots1 partials + fp16 feature store
    __shared__ float sAs[G1_BM], sAd[G1_BM];
    if (t < G1_BM) { sAs[t] = 0.f; sAd[t] = 0.f; }
    __syncthreads();
    int h = n0 >> 8;
    const float* avs = att_s + h * HIDC + (n0 & 255);
    const float* avd = att_d + h * HIDC + (n0 & 255);
#pragma unroll
    for (int mt = 0; mt < 2; mt++) {
        float ps0 = 0.f, pd0 = 0.f, ps1 = 0.f, pd1 = 0.f;
#pragma unroll
        for (int nt = 0; nt < 2; nt++) {
            int c = warp_n + nt * 8 + 2 * tig;
            float s0 = avs[c], s1 = avs[c + 1], dv0 = avd[c], dv1 = avd[c + 1];
            ps0 += acc[mt][nt][0] * s0 + acc[mt][nt][1] * s1;
            pd0 += acc[mt][nt][0] * dv0 + acc[mt][nt][1] * dv1;
            ps1 += acc[mt][nt][2] * s0 + acc[mt][nt][3] * s1;
            pd1 += acc[mt][nt][2] * dv0 + acc[mt][nt][3] * dv1;
        }
        int lr0 = warp_m + mt * 16 + g, lr1 = lr0 + 8;
        atomicAdd(&sAs[lr0], ps0); atomicAdd(&sAd[lr0], pd0);
        atomicAdd(&sAs[lr1], ps1); atomicAdd(&sAd[lr1], pd1);
        int r0 = m0 + lr0, r1 = m0 + lr1;
#pragma unroll
        for (int nt = 0; nt < 2; nt++) {
            int c = n0 + warp_n + nt * 8 + 2 * tig;
            if (r0 < NN) *(__half2*)&g_h1f[(size_t)r0 * D1 + c] =
                __floats2half2_rn(acc[mt][nt][0], acc[mt][nt][1]);
            if (r1 < NN) *(__half2*)&g_h1f[(size_t)r1 * D1 + c] =
                __floats2half2_rn(acc[mt][nt][2], acc[mt][nt][3]);
        }
    }
    __syncthreads();
    if (t < G1_BM && m0 + t < NN) {
        atomicAdd(&g_as1[(m0 + t) * NHEADS + h], sAs[t]);
        atomicAdd(&g_ad1[(m0 + t) * NHEADS + h], sAd[t]);
    }
}

// ---------------- GEMM2 (fp16 TC) + fused dots2 + fp16 store ----------------
__global__ void __launch_bounds__(256) k_gemm2_hf(const float* __restrict__ att_s,
                                                  const float* __restrict__ att_d) {
    cudaGridDependencySynchronize();
    __shared__ __half As2[128][40];
    __shared__ __half Bs2[128][40];
    int m0 = blockIdx.y * 128, n0 = blockIdx.x * 128;
    int t = threadIdx.x;
    int warp = t >> 5, lane = t & 31;
    int g = lane >> 2, tig = lane & 3;
    int warp_m = (warp & 1) * 64;
    int warp_n = (warp >> 1) * 32;

    float acc[4][4][4];
#pragma unroll
    for (int i = 0; i < 4; i++)
#pragma unroll
        for (int j = 0; j < 4; j++)
#pragma unroll
            for (int q = 0; q < 4; q++) acc[i][j][q] = 0.f;

    int ar = t >> 1, ak = (t & 1) * 16;

    for (int kb = 0; kb < D1; kb += 32) {
        {
            int gm = m0 + ar;
            uint4 v0 = make_uint4(0u, 0u, 0u, 0u), v1 = v0;
            if (gm < NN) {
                v0 = *(const uint4*)&g_x1f[(size_t)gm * D1 + kb + ak];
                v1 = *(const uint4*)&g_x1f[(size_t)gm * D1 + kb + ak + 8];
            }
            *(uint4*)&As2[ar][ak] = v0;
            *(uint4*)&As2[ar][ak + 8] = v1;
            uint4 w0 = *(const uint4*)&g_w2hT[(size_t)(n0 + ar) * D1 + kb + ak];
            uint4 w1 = *(const uint4*)&g_w2hT[(size_t)(n0 + ar) * D1 + kb + ak + 8];
            *(uint4*)&Bs2[ar][ak] = w0;
            *(uint4*)&Bs2[ar][ak + 8] = w1;
        }
        __syncthreads();
#pragma unroll
        for (int ks = 0; ks < 2; ks++) {
            int kk = ks * 16;
            unsigned a[4][4], b[4][2];
#pragma unroll
            for (int mt = 0; mt < 4; mt++) {
                int row = warp_m + mt * 16 + g;
                a[mt][0] = *(const unsigned*)&As2[row][kk + 2 * tig];
                a[mt][1] = *(const unsigned*)&As2[row + 8][kk + 2 * tig];
                a[mt][2] = *(const unsigned*)&As2[row][kk + 8 + 2 * tig];
                a[mt][3] = *(const unsigned*)&As2[row + 8][kk + 8 + 2 * tig];
            }
#pragma unroll
            for (int nt = 0; nt < 4; nt++) {
                int col = warp_n + nt * 8 + g;
                b[nt][0] = *(const unsigned*)&Bs2[col][kk + 2 * tig];
                b[nt][1] = *(const unsigned*)&Bs2[col][kk + 8 + 2 * tig];
            }
#pragma unroll
            for (int mt = 0; mt < 4; mt++)
#pragma unroll
                for (int nt = 0; nt < 4; nt++)
                    mma_f16(acc[mt][nt], a[mt], b[nt]);
        }
        __syncthreads();
    }

    __shared__ float sAs[128], sAd[128];
    if (t < 128) { sAs[t] = 0.f; sAd[t] = 0.f; }
    __syncthreads();
    const float* avs = att_s + n0;
    const float* avd = att_d + n0;
#pragma unroll
    for (int mt = 0; mt < 4; mt++) {
        float ps0 = 0.f, pd0 = 0.f, ps1 = 0.f, pd1 = 0.f;
#pragma unroll
        for (int nt = 0; nt < 4; nt++) {
            int c = warp_n + nt * 8 + 2 * tig;
            float s0 = avs[c], s1 = avs[c + 1], dv0 = avd[c], dv1 = avd[c + 1];
            ps0 += acc[mt][nt][0] * s0 + acc[mt][nt][1] * s1;
            pd0 += acc[mt][nt][0] * dv0 + acc[mt][nt][1] * dv1;
            ps1 += acc[mt][nt][2] * s0 + acc[mt][nt][3] * s1;
            pd1 += acc[mt][nt][2] * dv0 + acc[mt][nt][3] * dv1;
        }
        int lr0 = warp_m + mt * 16 + g, lr1 = lr0 + 8;
        atomicAdd(&sAs[lr0], ps0); atomicAdd(&sAd[lr0], pd0);
        atomicAdd(&sAs[lr1], ps1); atomicAdd(&sAd[lr1], pd1);
        int r0 = m0 + lr0, r1 = m0 + lr1;
#pragma unroll
        for (int nt = 0; nt < 4; nt++) {
            int c = n0 + warp_n + nt * 8 + 2 * tig;
            if (r0 < NN) *(__half2*)&g_h2f[(size_t)r0 * HIDC + c] =
                __floats2half2_rn(acc[mt][nt][0], acc[mt][nt][1]);
            if (r1 < NN) *(__half2*)&g_h2f[(size_t)r1 * HIDC + c] =
                __floats2half2_rn(acc[mt][nt][2], acc[mt][nt][3]);
        }
    }
    __syncthreads();
    if (t < 128 && m0 + t < NN) {
        atomicAdd(&g_as2[m0 + t], sAs[t]);
        atomicAdd(&g_ad2[m0 + t], sAd[t]);
    }
}

// ---------------- fused softmax + aggregation, layer 1 (no max pass) ----------------
__global__ void __launch_bounds__(256) k_agg1(const float* __restrict__ b1) {
    cudaGridDependencySynchronize();
    int dd = blockIdx.x, t = threadIdx.x;
    int beg = g_rowptr[dd], deg = g_rowptr[dd + 1] - beg, total = deg + 1;
    const float4* as4 = (const float4*)g_as1;
    float4 adv4 = ((const float4*)g_ad1)[dd];
    float ad[4] = {adv4.x, adv4.y, adv4.z, adv4.w};

    __shared__ float sred[8][4];
    int lane = t & 31, w = t >> 5;

    __shared__ float4 sw[256];
    __shared__ int ssrc[256];
    int hh = t >> 6;                 // head 0..3
    int f0 = (t & 63) * 4;           // feature start within head
    const size_t hoff = (size_t)hh * HIDC + f0;
    float acc[4] = {0.f, 0.f, 0.f, 0.f};
    float dl[4] = {0.f, 0.f, 0.f, 0.f};
    for (int base = 0; base < total; base += 256) {
        int j = base + t;
        int cn = min(256, total - base);
        if (j < total) {
            int s = (j < deg) ? g_csrsrc[beg + j] : dd;
            float4 a4 = as4[s];
            float e, w0, w1, w2, w3;
            e = a4.x + ad[0]; e = e > 0.f ? e : 0.2f * e; w0 = __expf(e); dl[0] += w0;
            e = a4.y + ad[1]; e = e > 0.f ? e : 0.2f * e; w1 = __expf(e); dl[1] += w1;
            e = a4.z + ad[2]; e = e > 0.f ? e : 0.2f * e; w2 = __expf(e); dl[2] += w2;
            e = a4.w + ad[3]; e = e > 0.f ? e : 0.2f * e; w3 = __expf(e); dl[3] += w3;
            sw[t] = make_float4(w0, w1, w2, w3);
            ssrc[t] = s;
        }
        __syncthreads();
#pragma unroll 8
        for (int j2 = 0; j2 < cn; j2++) {
            int s = ssrc[j2];
            float wv = ((const float*)&sw[j2])[hh];
            uint2 u = *(const uint2*)&g_h1f[(size_t)s * D1 + hoff];
            float2 fA = __half22float2(*(const __half2*)&u.x);
            float2 fB = __half22float2(*(const __half2*)&u.y);
            acc[0] += wv * fA.x; acc[1] += wv * fA.y;
            acc[2] += wv * fB.x; acc[3] += wv * fB.y;
        }
        __syncthreads();
    }
#pragma unroll
    for (int h = 0; h < 4; h++)
        for (int o = 16; o; o >>= 1) dl[h] += __shfl_xor_sync(0xffffffffu, dl[h], o);
    if (lane == 0) { sred[w][0] = dl[0]; sred[w][1] = dl[1]; sred[w][2] = dl[2]; sred[w][3] = dl[3]; }
    __syncthreads();
    __shared__ float den_s[4];
    if (t < 4) {
        float s = 0.f;
        for (int i = 0; i < 8; i++) s += sred[i][t];
        den_s[t] = s;
    }
    __syncthreads();
    {
        float inv = 1.0f / (den_s[hh] + 1e-16f);
        const float* bp = b1 + hh * HIDC + f0;
        float o0 = acc[0] * inv + bp[0];
        float o1 = acc[1] * inv + bp[1];
        float o2 = acc[2] * inv + bp[2];
        float o3 = acc[3] * inv + bp[3];
        o0 = o0 > 0.f ? o0 : 0.f; o1 = o1 > 0.f ? o1 : 0.f;
        o2 = o2 > 0.f ? o2 : 0.f; o3 = o3 > 0.f ? o3 : 0.f;
        __half2 h01 = __floats2half2_rn(o0, o1);
        __half2 h23 = __floats2half2_rn(o2, o3);
        uint2 uo = make_uint2(*(unsigned*)&h01, *(unsigned*)&h23);
        *(uint2*)&g_x1f[(size_t)dd * D1 + hoff] = uo;
    }
}

// ---------------- fused softmax + aggregation + pooling, layer 2 (no max pass) ----------------
__global__ void __launch_bounds__(256) k_agg2(const float* __restrict__ b2) {
    cudaGridDependencySynchronize();
    int dd = blockIdx.x, t = threadIdx.x;
    int beg = g_rowptr[dd], deg = g_rowptr[dd + 1] - beg, total = deg + 1;
    float adv = g_ad2[dd];
    __shared__ float sred[8];
    int lane = t & 31, w = t >> 5;

    __shared__ float sw[256];
    __shared__ int ssrc[256];
    float acc = 0.f, dl = 0.f;
    for (int base = 0; base < total; base += 256) {
        int j = base + t;
        int cn = min(256, total - base);
        if (j < total) {
            int s = (j < deg) ? g_csrsrc[beg + j] : dd;
            float e = g_as2[s] + adv; e = e > 0.f ? e : 0.2f * e;
            float wv = __expf(e);
            sw[t] = wv; ssrc[t] = s; dl += wv;
        }
        __syncthreads();
#pragma unroll 8
        for (int j2 = 0; j2 < cn; j2++) {
            acc += sw[j2] * __half2float(g_h2f[(size_t)ssrc[j2] * HIDC + t]);
        }
        __syncthreads();
    }
    for (int o = 16; o; o >>= 1) dl += __shfl_xor_sync(0xffffffffu, dl, o);
    if (lane == 0) sred[w] = dl;
    __syncthreads();
    __shared__ float den_s;
    if (t == 0) {
        float s = 0.f;
        for (int i = 0; i < 8; i++) s += sred[i];
        den_s = s;
    }
    __syncthreads();
    float o = acc / (den_s + 1e-16f) + b2[t];
    o = o > 0.f ? o : 0.f;
    atomicAdd(&g_pooled[t], o);
}

// ---------------- MLP head ----------------
__global__ void k_final(const float* __restrict__ Wv1, const float* __restrict__ bv1,
                        const float* __restrict__ Wv2, const float* __restrict__ bv2,
                        float* __restrict__ out) {
    cudaGridDependencySynchronize();
    __shared__ float red[128];
    int j = threadIdx.x;  // 128
    float acc = bv1[j];
    const float inv_n = 1.0f / (float)NN;
    for (int c = 0; c < HIDC; c++)
        acc += (g_pooled[c] * inv_n) * Wv1[c * 128 + j];
    float x = acc;
    float g = 0.5f * x * (1.0f + erff(x * 0.70710678118654752f));
    red[j] = g * Wv2[j];
    __syncthreads();
    for (int o = 64; o; o >>= 1) {
        if (j < o) red[j] += red[j + o];
        __syncthreads();
    }
    if (j == 0) out[0] = red[0] + bv2[0];
}

// ---------------- PDL launch helper ----------------
template <typename F, typename... Args>
static inline void launch_pdl(F kern, dim3 grid, dim3 block, Args... args) {
    cudaLaunchConfig_t cfg = {};
    cfg.gridDim = grid;
    cfg.blockDim = block;
    cfg.dynamicSmemBytes = 0;
    cfg.stream = 0;
    cudaLaunchAttribute at[1];
    at[0].id = cudaLaunchAttributeProgrammaticStreamSerialization;
    at[0].val.programmaticStreamSerializationAllowed = 1;
    cfg.attrs = at;
    cfg.numAttrs = 1;
    cudaLaunchKernelEx(&cfg, kern, args...);
}

// ---------------- launch ----------------
extern "C" void kernel_launch(void* const* d_in, const int* in_sizes, int n_in,
                              void* d_out, int out_size) {
    const float* X   = (const float*)d_in[0];
    const int*   ei  = (const int*)d_in[1];
    // d_in[2] = edge_attr (ignored: GATConv has no edge_dim)
    const float* W1  = (const float*)d_in[3];
    const float* as1 = (const float*)d_in[4];
    const float* ad1 = (const float*)d_in[5];
    const float* b1  = (const float*)d_in[6];
    const float* W2  = (const float*)d_in[7];
    const float* as2 = (const float*)d_in[8];
    const float* ad2 = (const float*)d_in[9];
    const float* b2  = (const float*)d_in[10];
    const float* Wv1 = (const float*)d_in[11];
    const float* bv1 = (const float*)d_in[12];
    const float* Wv2 = (const float*)d_in[13];
    const float* bv2 = (const float*)d_in[14];
    float* out = (float*)d_out;

    k_init<<<(D1 * HIDC + 255) / 256, 256>>>(W2);
    launch_pdl(k_hist, dim3((EE + 255) / 256), dim3(256), ei);
    launch_pdl(k_scan, dim3(1), dim3(1024));
    launch_pdl(k_fill, dim3((EE + 255) / 256), dim3(256), ei);

    launch_pdl(k_gemm1_tc, dim3(D1 / G1_BN, (NN + G1_BM - 1) / G1_BM), dim3(256),
               X, W1, as1, ad1);
    launch_pdl(k_agg1, dim3(NN), dim3(256), b1);

    launch_pdl(k_gemm2_hf, dim3(2, (NN + 127) / 128), dim3(256), as2, ad2);
    launch_pdl(k_agg2, dim3(NN), dim3(256), b2);

    launch_pdl(k_final, dim3(1), dim3(128), Wv1, bv1, Wv2, bv2, out);
}

// round 15
// speedup vs baseline: 1.0469x; 1.0234x over previous
#include <cuda_runtime.h>
#include <cuda_fp16.h>
#include <math.h>

#define NN 10000
#define EE 160000
#define FIN 70
#define HIDC 256
#define NHEADS 4
#define D1 1024   // NHEADS*HIDC

// ---------------- scratch (device globals; no allocations) ----------------
__device__ __half g_h1f[(size_t)NN * D1];   // layer1 pre-attention features (fp16)
__device__ __half g_x1f[(size_t)NN * D1];   // layer1 output relu (fp16)
__device__ __half g_h2f[(size_t)NN * HIDC]; // layer2 pre-attention features (fp16)
__device__ __half g_w2hT[(size_t)HIDC * D1];// W2 transposed fp16: [n][k]
__device__ float g_as1[NN * NHEADS];
__device__ float g_ad1[NN * NHEADS];
__device__ float g_as2[NN];
__device__ float g_ad2[NN];
__device__ int   g_cnt[NN];
__device__ int   g_rowptr[NN + 1];
__device__ int   g_fill[NN];
__device__ int   g_csrsrc[EE];
__device__ float g_pooled[HIDC];

// ---------------- mma helper ----------------
__device__ __forceinline__ void mma_f16(float d[4], const unsigned a[4], const unsigned b[2]) {
    asm volatile(
        "mma.sync.aligned.m16n8k16.row.col.f32.f16.f16.f32 "
        "{%0,%1,%2,%3},{%4,%5,%6,%7},{%8,%9},{%0,%1,%2,%3};"
        : "+f"(d[0]), "+f"(d[1]), "+f"(d[2]), "+f"(d[3])
        : "r"(a[0]), "r"(a[1]), "r"(a[2]), "r"(a[3]), "r"(b[0]), "r"(b[1]));
}

// ---------------- preamble: zero scratch + W2 -> fp16 transposed ----------------
__global__ void k_init(const float* __restrict__ W2) {
    int i = blockIdx.x * blockDim.x + threadIdx.x;    // D1*HIDC threads
    if (i < D1 * HIDC) {
        int k = i >> 8, n = i & 255;
        g_w2hT[(size_t)n * D1 + k] = __float2half(W2[i]);
    }
    if (i < NN) { g_cnt[i] = 0; g_as2[i] = 0.f; g_ad2[i] = 0.f; }
    if (i < NN * NHEADS) { g_as1[i] = 0.f; g_ad1[i] = 0.f; }
    if (i < HIDC) g_pooled[i] = 0.f;
}

// ---------------- CSR build ----------------
__global__ void k_hist(const int* __restrict__ ei) {
    int e = blockIdx.x * blockDim.x + threadIdx.x;
    if (e < EE) atomicAdd(&g_cnt[ei[EE + e]], 1);
}

// single-pass scan: 1024 threads x 10 elements each (covers NN=10000)
#define SCAN_C 10
__global__ void k_scan() {
    __shared__ int wsum[32];
    int t = threadIdx.x, lane = t & 31, w = t >> 5;
    int base = t * SCAN_C;
    int v[SCAN_C];
    int s = 0;
#pragma unroll
    for (int k = 0; k < SCAN_C; k++) {
        int i = base + k;
        v[k] = (i < NN) ? g_cnt[i] : 0;
        s += v[k];
    }
    int x = s;
#pragma unroll
    for (int o = 1; o < 32; o <<= 1) {
        int y = __shfl_up_sync(0xffffffffu, x, o);
        if (lane >= o) x += y;
    }
    if (lane == 31) wsum[w] = x;
    __syncthreads();
    if (w == 0) {
        int ws = wsum[lane];
#pragma unroll
        for (int o = 1; o < 32; o <<= 1) {
            int y = __shfl_up_sync(0xffffffffu, ws, o);
            if (lane >= o) ws += y;
        }
        wsum[lane] = ws;
    }
    __syncthreads();
    int run = x - s + (w ? wsum[w - 1] : 0);
#pragma unroll
    for (int k = 0; k < SCAN_C; k++) {
        int i = base + k;
        if (i < NN) { g_rowptr[i] = run; g_fill[i] = run; }
        run += v[k];
    }
    if (t == 1023) g_rowptr[NN] = run;
}

__global__ void k_fill(const int* __restrict__ ei) {
    int e = blockIdx.x * blockDim.x + threadIdx.x;
    if (e < EE) {
        int d = ei[EE + e];
        int p = atomicAdd(&g_fill[d], 1);
        g_csrsrc[p] = ei[e];
    }
}

// ---------------- GEMM1 (fp16 TC, 64x64 tiles) + fused dots1 + fp16 store ----------------
// Same 64x64 tile / 8-warp / epilogue structure as the verified tf32 version;
// only the mma dtype changed (m16n8k16 fp16, K padded 70->80) and smem is fp16.
#define G1_BM 64
#define G1_BN 64
#define G1_KP 80
__global__ void __launch_bounds__(256) k_gemm1_hf(const float* __restrict__ X,
                                                  const float* __restrict__ W1,
                                                  const float* __restrict__ att_s,
                                                  const float* __restrict__ att_d) {
    __shared__ __half As[G1_BM][G1_KP + 8];   // [m][k] stride 88
    __shared__ __half Bs[G1_BN][G1_KP + 8];   // [n][k] stride 88
    int m0 = blockIdx.y * G1_BM, n0 = blockIdx.x * G1_BN;
    int t = threadIdx.x;
    int warp = t >> 5, lane = t & 31;
    int g = lane >> 2, tig = lane & 3;
    int warp_m = (warp & 1) * 32;
    int warp_n = (warp >> 1) * 16;

    // A fill: [m][k], zero-pad k to 80
    for (int idx = t; idx < G1_BM * G1_KP; idx += 256) {
        int r = idx / G1_KP, c = idx - r * G1_KP;
        int gm = m0 + r;
        float v = 0.f;
        if (c < FIN && gm < NN) v = X[(size_t)gm * FIN + c];
        As[r][c] = __float2half(v);
    }
    // B fill: W1 is [k][n] global -> Bs[n][k]
    for (int idx = t; idx < G1_BN * G1_KP; idx += 256) {
        int k = idx >> 6, n = idx & 63;   // k 0..79, n 0..63
        float v = (k < FIN) ? W1[(size_t)k * D1 + n0 + n] : 0.f;
        Bs[n][k] = __float2half(v);
    }
    __syncthreads();

    float acc[2][2][4];
#pragma unroll
    for (int i = 0; i < 2; i++)
#pragma unroll
        for (int j = 0; j < 2; j++)
#pragma unroll
            for (int q = 0; q < 4; q++) acc[i][j][q] = 0.f;

#pragma unroll
    for (int ks = 0; ks < 5; ks++) {
        int kk = ks * 16;
        unsigned a[2][4], b[2][2];
#pragma unroll
        for (int mt = 0; mt < 2; mt++) {
            int row = warp_m + mt * 16 + g;
            a[mt][0] = *(const unsigned*)&As[row][kk + 2 * tig];
            a[mt][1] = *(const unsigned*)&As[row + 8][kk + 2 * tig];
            a[mt][2] = *(const unsigned*)&As[row][kk + 8 + 2 * tig];
            a[mt][3] = *(const unsigned*)&As[row + 8][kk + 8 + 2 * tig];
        }
#pragma unroll
        for (int nt = 0; nt < 2; nt++) {
            int col = warp_n + nt * 8 + g;
            b[nt][0] = *(const unsigned*)&Bs[col][kk + 2 * tig];
            b[nt][1] = *(const unsigned*)&Bs[col][kk + 8 + 2 * tig];
        }
#pragma unroll
        for (int mt = 0; mt < 2; mt++)
#pragma unroll
            for (int nt = 0; nt < 2; nt++)
                mma_f16(acc[mt][nt], a[mt], b[nt]);
    }

    // fused dots1 partials + fp16 feature store (identical to verified epilogue)
    __shared__ float sAs[G1_BM], sAd[G1_BM];
    if (t < G1_BM) { sAs[t] = 0.f; sAd[t] = 0.f; }
    __syncthreads();
    int h = n0 >> 8;
    const float* avs = att_s + h * HIDC + (n0 & 255);
    const float* avd = att_d + h * HIDC + (n0 & 255);
#pragma unroll
    for (int mt = 0; mt < 2; mt++) {
        float ps0 = 0.f, pd0 = 0.f, ps1 = 0.f, pd1 = 0.f;
#pragma unroll
        for (int nt = 0; nt < 2; nt++) {
            int c = warp_n + nt * 8 + 2 * tig;
            float s0 = avs[c], s1 = avs[c + 1], dv0 = avd[c], dv1 = avd[c + 1];
            ps0 += acc[mt][nt][0] * s0 + acc[mt][nt][1] * s1;
            pd0 += acc[mt][nt][0] * dv0 + acc[mt][nt][1] * dv1;
            ps1 += acc[mt][nt][2] * s0 + acc[mt][nt][3] * s1;
            pd1 += acc[mt][nt][2] * dv0 + acc[mt][nt][3] * dv1;
        }
        int lr0 = warp_m + mt * 16 + g, lr1 = lr0 + 8;
        atomicAdd(&sAs[lr0], ps0); atomicAdd(&sAd[lr0], pd0);
        atomicAdd(&sAs[lr1], ps1); atomicAdd(&sAd[lr1], pd1);
        int r0 = m0 + lr0, r1 = m0 + lr1;
#pragma unroll
        for (int nt = 0; nt < 2; nt++) {
            int c = n0 + warp_n + nt * 8 + 2 * tig;
            if (r0 < NN) *(__half2*)&g_h1f[(size_t)r0 * D1 + c] =
                __floats2half2_rn(acc[mt][nt][0], acc[mt][nt][1]);
            if (r1 < NN) *(__half2*)&g_h1f[(size_t)r1 * D1 + c] =
                __floats2half2_rn(acc[mt][nt][2], acc[mt][nt][3]);
        }
    }
    __syncthreads();
    if (t < G1_BM && m0 + t < NN) {
        atomicAdd(&g_as1[(m0 + t) * NHEADS + h], sAs[t]);
        atomicAdd(&g_ad1[(m0 + t) * NHEADS + h], sAd[t]);
    }
}

// ---------------- GEMM2 (fp16 TC) + fused dots2 + fp16 store ----------------
__global__ void __launch_bounds__(256) k_gemm2_hf(const float* __restrict__ att_s,
                                                  const float* __restrict__ att_d) {
    __shared__ __half As2[128][40];
    __shared__ __half Bs2[128][40];
    int m0 = blockIdx.y * 128, n0 = blockIdx.x * 128;
    int t = threadIdx.x;
    int warp = t >> 5, lane = t & 31;
    int g = lane >> 2, tig = lane & 3;
    int warp_m = (warp & 1) * 64;
    int warp_n = (warp >> 1) * 32;

    float acc[4][4][4];
#pragma unroll
    for (int i = 0; i < 4; i++)
#pragma unroll
        for (int j = 0; j < 4; j++)
#pragma unroll
            for (int q = 0; q < 4; q++) acc[i][j][q] = 0.f;

    int ar = t >> 1, ak = (t & 1) * 16;

    for (int kb = 0; kb < D1; kb += 32) {
        {
            int gm = m0 + ar;
            uint4 v0 = make_uint4(0u, 0u, 0u, 0u), v1 = v0;
            if (gm < NN) {
                v0 = *(const uint4*)&g_x1f[(size_t)gm * D1 + kb + ak];
                v1 = *(const uint4*)&g_x1f[(size_t)gm * D1 + kb + ak + 8];
            }
            *(uint4*)&As2[ar][ak] = v0;
            *(uint4*)&As2[ar][ak + 8] = v1;
            uint4 w0 = *(const uint4*)&g_w2hT[(size_t)(n0 + ar) * D1 + kb + ak];
            uint4 w1 = *(const uint4*)&g_w2hT[(size_t)(n0 + ar) * D1 + kb + ak + 8];
            *(uint4*)&Bs2[ar][ak] = w0;
            *(uint4*)&Bs2[ar][ak + 8] = w1;
        }
        __syncthreads();
#pragma unroll
        for (int ks = 0; ks < 2; ks++) {
            int kk = ks * 16;
            unsigned a[4][4], b[4][2];
#pragma unroll
            for (int mt = 0; mt < 4; mt++) {
                int row = warp_m + mt * 16 + g;
                a[mt][0] = *(const unsigned*)&As2[row][kk + 2 * tig];
                a[mt][1] = *(const unsigned*)&As2[row + 8][kk + 2 * tig];
                a[mt][2] = *(const unsigned*)&As2[row][kk + 8 + 2 * tig];
                a[mt][3] = *(const unsigned*)&As2[row + 8][kk + 8 + 2 * tig];
            }
#pragma unroll
            for (int nt = 0; nt < 4; nt++) {
                int col = warp_n + nt * 8 + g;
                b[nt][0] = *(const unsigned*)&Bs2[col][kk + 2 * tig];
                b[nt][1] = *(const unsigned*)&Bs2[col][kk + 8 + 2 * tig];
            }
#pragma unroll
            for (int mt = 0; mt < 4; mt++)
#pragma unroll
                for (int nt = 0; nt < 4; nt++)
                    mma_f16(acc[mt][nt], a[mt], b[nt]);
        }
        __syncthreads();
    }

    __shared__ float sAs[128], sAd[128];
    if (t < 128) { sAs[t] = 0.f; sAd[t] = 0.f; }
    __syncthreads();
    const float* avs = att_s + n0;
    const float* avd = att_d + n0;
#pragma unroll
    for (int mt = 0; mt < 4; mt++) {
        float ps0 = 0.f, pd0 = 0.f, ps1 = 0.f, pd1 = 0.f;
#pragma unroll
        for (int nt = 0; nt < 4; nt++) {
            int c = warp_n + nt * 8 + 2 * tig;
            float s0 = avs[c], s1 = avs[c + 1], dv0 = avd[c], dv1 = avd[c + 1];
            ps0 += acc[mt][nt][0] * s0 + acc[mt][nt][1] * s1;
            pd0 += acc[mt][nt][0] * dv0 + acc[mt][nt][1] * dv1;
            ps1 += acc[mt][nt][2] * s0 + acc[mt][nt][3] * s1;
            pd1 += acc[mt][nt][2] * dv0 + acc[mt][nt][3] * dv1;
        }
        int lr0 = warp_m + mt * 16 + g, lr1 = lr0 + 8;
        atomicAdd(&sAs[lr0], ps0); atomicAdd(&sAd[lr0], pd0);
        atomicAdd(&sAs[lr1], ps1); atomicAdd(&sAd[lr1], pd1);
        int r0 = m0 + lr0, r1 = m0 + lr1;
#pragma unroll
        for (int nt = 0; nt < 4; nt++) {
            int c = n0 + warp_n + nt * 8 + 2 * tig;
            if (r0 < NN) *(__half2*)&g_h2f[(size_t)r0 * HIDC + c] =
                __floats2half2_rn(acc[mt][nt][0], acc[mt][nt][1]);
            if (r1 < NN) *(__half2*)&g_h2f[(size_t)r1 * HIDC + c] =
                __floats2half2_rn(acc[mt][nt][2], acc[mt][nt][3]);
        }
    }
    __syncthreads();
    if (t < 128 && m0 + t < NN) {
        atomicAdd(&g_as2[m0 + t], sAs[t]);
        atomicAdd(&g_ad2[m0 + t], sAd[t]);
    }
}

// ---------------- fused softmax + aggregation, layer 1 (no max pass) ----------------
__global__ void __launch_bounds__(256) k_agg1(const float* __restrict__ b1) {
    int dd = blockIdx.x, t = threadIdx.x;
    int beg = g_rowptr[dd], deg = g_rowptr[dd + 1] - beg, total = deg + 1;
    const float4* as4 = (const float4*)g_as1;
    float4 adv4 = ((const float4*)g_ad1)[dd];
    float ad[4] = {adv4.x, adv4.y, adv4.z, adv4.w};

    __shared__ float sred[8][4];
    int lane = t & 31, w = t >> 5;

    __shared__ float4 sw[256];
    __shared__ int ssrc[256];
    int hh = t >> 6;                 // head 0..3
    int f0 = (t & 63) * 4;           // feature start within head
    const size_t hoff = (size_t)hh * HIDC + f0;
    float acc[4] = {0.f, 0.f, 0.f, 0.f};
    float dl[4] = {0.f, 0.f, 0.f, 0.f};
    for (int base = 0; base < total; base += 256) {
        int j = base + t;
        int cn = min(256, total - base);
        if (j < total) {
            int s = (j < deg) ? g_csrsrc[beg + j] : dd;
            float4 a4 = as4[s];
            float e, w0, w1, w2, w3;
            e = a4.x + ad[0]; e = e > 0.f ? e : 0.2f * e; w0 = __expf(e); dl[0] += w0;
            e = a4.y + ad[1]; e = e > 0.f ? e : 0.2f * e; w1 = __expf(e); dl[1] += w1;
            e = a4.z + ad[2]; e = e > 0.f ? e : 0.2f * e; w2 = __expf(e); dl[2] += w2;
            e = a4.w + ad[3]; e = e > 0.f ? e : 0.2f * e; w3 = __expf(e); dl[3] += w3;
            sw[t] = make_float4(w0, w1, w2, w3);
            ssrc[t] = s;
        }
        __syncthreads();
#pragma unroll 8
        for (int j2 = 0; j2 < cn; j2++) {
            int s = ssrc[j2];
            float wv = ((const float*)&sw[j2])[hh];
            uint2 u = *(const uint2*)&g_h1f[(size_t)s * D1 + hoff];
            float2 fA = __half22float2(*(const __half2*)&u.x);
            float2 fB = __half22float2(*(const __half2*)&u.y);
            acc[0] += wv * fA.x; acc[1] += wv * fA.y;
            acc[2] += wv * fB.x; acc[3] += wv * fB.y;
        }
        __syncthreads();
    }
#pragma unroll
    for (int h = 0; h < 4; h++)
        for (int o = 16; o; o >>= 1) dl[h] += __shfl_xor_sync(0xffffffffu, dl[h], o);
    if (lane == 0) { sred[w][0] = dl[0]; sred[w][1] = dl[1]; sred[w][2] = dl[2]; sred[w][3] = dl[3]; }
    __syncthreads();
    __shared__ float den_s[4];
    if (t < 4) {
        float s = 0.f;
        for (int i = 0; i < 8; i++) s += sred[i][t];
        den_s[t] = s;
    }
    __syncthreads();
    {
        float inv = 1.0f / (den_s[hh] + 1e-16f);
        const float* bp = b1 + hh * HIDC + f0;
        float o0 = acc[0] * inv + bp[0];
        float o1 = acc[1] * inv + bp[1];
        float o2 = acc[2] * inv + bp[2];
        float o3 = acc[3] * inv + bp[3];
        o0 = o0 > 0.f ? o0 : 0.f; o1 = o1 > 0.f ? o1 : 0.f;
        o2 = o2 > 0.f ? o2 : 0.f; o3 = o3 > 0.f ? o3 : 0.f;
        __half2 h01 = __floats2half2_rn(o0, o1);
        __half2 h23 = __floats2half2_rn(o2, o3);
        uint2 uo = make_uint2(*(unsigned*)&h01, *(unsigned*)&h23);
        *(uint2*)&g_x1f[(size_t)dd * D1 + hoff] = uo;
    }
}

// ---------------- fused softmax + aggregation + pooling, layer 2 (no max pass) ----------------
__global__ void __launch_bounds__(256) k_agg2(const float* __restrict__ b2) {
    int dd = blockIdx.x, t = threadIdx.x;
    int beg = g_rowptr[dd], deg = g_rowptr[dd + 1] - beg, total = deg + 1;
    float adv = g_ad2[dd];
    __shared__ float sred[8];
    int lane = t & 31, w = t >> 5;

    __shared__ float sw[256];
    __shared__ int ssrc[256];
    float acc = 0.f, dl = 0.f;
    for (int base = 0; base < total; base += 256) {
        int j = base + t;
        int cn = min(256, total - base);
        if (j < total) {
            int s = (j < deg) ? g_csrsrc[beg + j] : dd;
            float e = g_as2[s] + adv; e = e > 0.f ? e : 0.2f * e;
            float wv = __expf(e);
            sw[t] = wv; ssrc[t] = s; dl += wv;
        }
        __syncthreads();
#pragma unroll 8
        for (int j2 = 0; j2 < cn; j2++) {
            acc += sw[j2] * __half2float(g_h2f[(size_t)ssrc[j2] * HIDC + t]);
        }
        __syncthreads();
    }
    for (int o = 16; o; o >>= 1) dl += __shfl_xor_sync(0xffffffffu, dl, o);
    if (lane == 0) sred[w] = dl;
    __syncthreads();
    __shared__ float den_s;
    if (t == 0) {
        float s = 0.f;
        for (int i = 0; i < 8; i++) s += sred[i];
        den_s = s;
    }
    __syncthreads();
    float o = acc / (den_s + 1e-16f) + b2[t];
    o = o > 0.f ? o : 0.f;
    atomicAdd(&g_pooled[t], o);
}

// ---------------- MLP head ----------------
__global__ void k_final(const float* __restrict__ Wv1, const float* __restrict__ bv1,
                        const float* __restrict__ Wv2, const float* __restrict__ bv2,
                        float* __restrict__ out) {
    __shared__ float red[128];
    int j = threadIdx.x;  // 128
    float acc = bv1[j];
    const float inv_n = 1.0f / (float)NN;
    for (int c = 0; c < HIDC; c++)
        acc += (g_pooled[c] * inv_n) * Wv1[c * 128 + j];
    float x = acc;
    float g = 0.5f * x * (1.0f + erff(x * 0.70710678118654752f));
    red[j] = g * Wv2[j];
    __syncthreads();
    for (int o = 64; o; o >>= 1) {
        if (j < o) red[j] += red[j + o];
        __syncthreads();
    }
    if (j == 0) out[0] = red[0] + bv2[0];
}

// ---------------- launch ----------------
extern "C" void kernel_launch(void* const* d_in, const int* in_sizes, int n_in,
                              void* d_out, int out_size) {
    const float* X   = (const float*)d_in[0];
    const int*   ei  = (const int*)d_in[1];
    // d_in[2] = edge_attr (ignored: GATConv has no edge_dim)
    const float* W1  = (const float*)d_in[3];
    const float* as1 = (const float*)d_in[4];
    const float* ad1 = (const float*)d_in[5];
    const float* b1  = (const float*)d_in[6];
    const float* W2  = (const float*)d_in[7];
    const float* as2 = (const float*)d_in[8];
    const float* ad2 = (const float*)d_in[9];
    const float* b2  = (const float*)d_in[10];
    const float* Wv1 = (const float*)d_in[11];
    const float* bv1 = (const float*)d_in[12];
    const float* Wv2 = (const float*)d_in[13];
    const float* bv2 = (const float*)d_in[14];
    float* out = (float*)d_out;

    k_init<<<(D1 * HIDC + 255) / 256, 256>>>(W2);
    k_hist<<<(EE + 255) / 256, 256>>>(ei);
    k_scan<<<1, 1024>>>();
    k_fill<<<(EE + 255) / 256, 256>>>(ei);

    k_gemm1_hf<<<dim3(D1 / G1_BN, (NN + G1_BM - 1) / G1_BM), 256>>>(X, W1, as1, ad1);
    k_agg1<<<NN, 256>>>(b1);

    k_gemm2_hf<<<dim3(2, (NN + 127) / 128), 256>>>(as2, ad2);
    k_agg2<<<NN, 256>>>(b2);

    k_final<<<1, 128>>>(Wv1, bv1, Wv2, bv2, out);
}